// round 4
// baseline (speedup 1.0000x reference)
#include <cuda_runtime.h>
#include <math_constants.h>

#define BB 64
#define NN 512
#define NTHREADS 256

__global__ void init_out_kernel(float* out) {
    out[0] = 0.0f;
    out[1] = 0.0f;
}

__global__ __launch_bounds__(NTHREADS) void chamfer_split_pid_kernel(
    const float4* __restrict__ target,   // [B*N] float4 (D=4)
    const float4* __restrict__ reco,     // [B*N] float4
    const int* __restrict__ in_pid,      // [B*N]
    const int* __restrict__ out_pid,     // [B*N]
    float* __restrict__ out)             // [2]: loss_nonzero, loss_zero
{
    __shared__ float4 gt[NN];            // target points grouped by in_pid
    __shared__ float4 gr[NN];            // reco points grouped by out_pid
    __shared__ unsigned char gct[NN];    // class of grouped target entry
    __shared__ unsigned char gcr[NN];    // class of grouped reco entry
    __shared__ int cx[5], cy[5];         // class counts
    __shared__ int ox[6], oy[6];         // group offsets
    __shared__ int curx[5], cury[5];     // scatter cursors
    __shared__ float sx[5], sy[5];       // sum of norms per class (full batch)
    __shared__ float sacc[5];            // this CTA's direction partial sums

    const int b = blockIdx.x >> 1;       // batch index
    const int half = blockIdx.x & 1;     // 0: x->y direction, 1: y->x direction
    const int tid = threadIdx.x;
    const int base = b * NN;

    if (tid < 5) {
        cx[tid] = 0; cy[tid] = 0;
        sx[tid] = 0.0f; sy[tid] = 0.0f;
        sacc[tid] = 0.0f;
    }
    __syncthreads();

    // ---- Pass 1: class counts (full batch; duplicated across the 2 CTAs) ----
    for (int i = tid; i < NN; i += NTHREADS) {
        atomicAdd(&cx[in_pid[base + i]], 1);
        atomicAdd(&cy[out_pid[base + i]], 1);
    }
    __syncthreads();

    if (tid == 0) {
        int a = 0, c = 0;
        #pragma unroll
        for (int p = 0; p < 5; p++) {
            ox[p] = a; a += cx[p];
            oy[p] = c; c += cy[p];
            curx[p] = ox[p];
            cury[p] = oy[p];
        }
        ox[5] = a; oy[5] = c;
    }
    __syncthreads();

    // ---- Pass 2: scatter into pid-contiguous groups + norm sums ----
    // Scatter order within a group is arbitrary (atomicAdd), which is safe:
    // this CTA iterates its OWN permutation for the full direction it owns,
    // and group membership is order-invariant for the min-search.
    for (int i = tid; i < NN; i += NTHREADS) {
        int p = in_pid[base + i];
        float4 t = target[base + i];
        int pos = atomicAdd(&curx[p], 1);
        gt[pos] = t;
        gct[pos] = (unsigned char)p;
        float nt = sqrtf(t.x * t.x + t.y * t.y + t.z * t.z + t.w * t.w);
        atomicAdd(&sx[p], nt);

        int q = out_pid[base + i];
        float4 r = reco[base + i];
        int qpos = atomicAdd(&cury[q], 1);
        gr[qpos] = r;
        gcr[qpos] = (unsigned char)q;
        float nr = sqrtf(r.x * r.x + r.y * r.y + r.z * r.z + r.w * r.w);
        atomicAdd(&sy[q], nr);
    }
    __syncthreads();

    if (half == 0) {
        // ---- Direction x->y: every target entry (class p>=1) vs reco group p ----
        // Entries are pid-grouped: consecutive lanes share a class, so the
        // inner-loop LDS reads are warp-uniform (free broadcast, no conflicts).
        #pragma unroll
        for (int c = 0; c < NN / NTHREADS; c++) {
            int k = c * NTHREADS + tid;
            int p = gct[k];
            int jb = oy[p], je = oy[p + 1];
            if (p != 0 && jb != je) {      // cy[p]==0: only_x branch handles it
                float4 t = gt[k];
                float m = CUDART_INF_F;
                #pragma unroll 8
                for (int j = jb; j < je; j++) {
                    float4 r = gr[j];
                    float dx = t.x - r.x, dy = t.y - r.y, dz = t.z - r.z, dw = t.w - r.w;
                    float d2 = dx * dx + dy * dy + dz * dz + dw * dw;
                    m = fminf(m, d2);
                }
                atomicAdd(&sacc[p], sqrtf(m));   // sacc[p] == sum_xy for class p
            }
        }
    } else {
        // ---- Direction y->x: every reco entry (class p>=1) vs target group p ----
        #pragma unroll
        for (int c = 0; c < NN / NTHREADS; c++) {
            int k = c * NTHREADS + tid;
            int p = gcr[k];
            int jb = ox[p], je = ox[p + 1];
            if (p != 0 && jb != je) {      // cx[p]==0: only_y branch handles it
                float4 r = gr[k];
                float m = CUDART_INF_F;
                #pragma unroll 8
                for (int j = jb; j < je; j++) {
                    float4 t = gt[j];
                    float dx = t.x - r.x, dy = t.y - r.y, dz = t.z - r.z, dw = t.w - r.w;
                    float d2 = dx * dx + dy * dy + dz * dz + dw * dw;
                    m = fminf(m, d2);
                }
                atomicAdd(&sacc[p], sqrtf(m));   // sacc[p] == sum_yx for class p
            }
        }
    }
    __syncthreads();

    // ---- Per-batch combine + global accumulate ----
    // Both CTAs see identical counts and sx/sy, so branch conditions agree.
    // half==0 contributes: 0.5*sum_xy/cy (both-branch), only_x (cy==0), loss_zero.
    // half==1 contributes: 0.5*sum_yx/cx (both-branch), only_y (cx==0 && cy>0).
    if (tid == 0) {
        const float invB = 1.0f / (float)BB;
        float lnz = 0.0f;
        #pragma unroll
        for (int p = 1; p < 5; p++) {
            if (cy[p] == 0) {
                if (half == 0) lnz += sx[p] / (float)max(1, cx[p]);
            } else if (cx[p] == 0) {
                if (half == 1) lnz += sy[p] / (float)max(1, cy[p]);
            } else {
                lnz += (half == 0) ? 0.5f * (sacc[p] / (float)cy[p])
                                   : 0.5f * (sacc[p] / (float)cx[p]);
            }
        }
        atomicAdd(&out[0], lnz * invB);
        if (half == 0) {
            float lz = sy[0] / (float)max(1, cy[0]);
            atomicAdd(&out[1], lz * invB);
        }
    }
}

extern "C" void kernel_launch(void* const* d_in, const int* in_sizes, int n_in,
                              void* d_out, int out_size) {
    const float4* target = (const float4*)d_in[0];
    const float4* reco   = (const float4*)d_in[1];
    const int* in_pid    = (const int*)d_in[2];
    const int* out_pid   = (const int*)d_in[3];
    float* out = (float*)d_out;

    init_out_kernel<<<1, 32>>>(out);
    chamfer_split_pid_kernel<<<BB * 2, NTHREADS>>>(target, reco, in_pid, out_pid, out);
}